// round 1
// baseline (speedup 1.0000x reference)
#include <cuda_runtime.h>

// GraphNudger: out[b,d] = ETA * ||grad_b|| * sum_s W[d,s] * sim[b,s]
//   sim[b,s] = (cos(H_b, S_s) + 1)/2,  W[d,s] = sum of edge weights (d,s)
//
// B=64, F=512, S=8192, E=500000, D=1024 (fixed shapes for this problem).

#define Bb 64
#define Ff 512
#define Ss 8192
#define Dd 1024
#define NSPLIT 8
#define KC 32

// Device scratch (no allocations allowed in kernel_launch)
__device__ float g_W[(size_t)Dd * Ss];              // 32 MB dense edge-weight matrix
__device__ float g_sim[(size_t)Bb * Ss];            // 2 MB similarity matrix
__device__ float g_part[(size_t)NSPLIT * Bb * Dd];  // split-K partials (deterministic)
__device__ float g_sinv[Ss];
__device__ float g_hinv[Bb];
__device__ float g_gs[Bb];                          // ETA * ||grad_b||

// ---------------------------------------------------------------------------
// Zero W (rebuilt every call)
// ---------------------------------------------------------------------------
__global__ void zero_w_kernel() {
    const size_t n = (size_t)Dd * Ss / 4;
    float4 z = make_float4(0.f, 0.f, 0.f, 0.f);
    float4* p = reinterpret_cast<float4*>(g_W);
    for (size_t i = (size_t)blockIdx.x * blockDim.x + threadIdx.x; i < n;
         i += (size_t)gridDim.x * blockDim.x)
        p[i] = z;
}

// ---------------------------------------------------------------------------
// Row norms: sign rows -> 1/(||x||+eps), heat rows -> 1/(||x||+eps),
// grad rows -> ETA*||x||. One warp per row.
// ---------------------------------------------------------------------------
__global__ void norms_kernel(const float* __restrict__ sign,
                             const float* __restrict__ heat,
                             const float* __restrict__ grad) {
    int warp = (blockIdx.x * blockDim.x + threadIdx.x) >> 5;
    int lane = threadIdx.x & 31;
    const int total = Ss + 2 * Bb;
    if (warp >= total) return;
    const float* base;
    if (warp < Ss)           base = sign + (size_t)warp * Ff;
    else if (warp < Ss + Bb) base = heat + (size_t)(warp - Ss) * Ff;
    else                     base = grad + (size_t)(warp - Ss - Bb) * Ff;
    const float4* p = reinterpret_cast<const float4*>(base);
    float s = 0.f;
#pragma unroll
    for (int i = 0; i < Ff / 128; i++) {
        float4 v = p[lane + i * 32];
        s += v.x * v.x + v.y * v.y + v.z * v.z + v.w * v.w;
    }
#pragma unroll
    for (int o = 16; o; o >>= 1) s += __shfl_xor_sync(0xffffffff, s, o);
    if (lane == 0) {
        if (warp < Ss)           g_sinv[warp]           = 1.0f / (sqrtf(s) + 1e-8f);
        else if (warp < Ss + Bb) g_hinv[warp - Ss]      = 1.0f / (sqrtf(s) + 1e-8f);
        else                     g_gs[warp - Ss - Bb]   = 0.01f * sqrtf(s);
    }
}

// ---------------------------------------------------------------------------
// Scatter edges into W: 500k atomics spread over ~8M addresses (no contention)
// ---------------------------------------------------------------------------
__global__ void scatter_kernel(const float* __restrict__ w,
                               const int* __restrict__ dis,
                               const int* __restrict__ sgn, int E) {
    for (int e = blockIdx.x * blockDim.x + threadIdx.x; e < E;
         e += gridDim.x * blockDim.x)
        atomicAdd(&g_W[(size_t)dis[e] * Ss + sgn[e]], w[e]);
}

// ---------------------------------------------------------------------------
// GEMM1: sim[b,s] = (hinv_b * sinv_s * (H_b . S_s) + 1) * 0.5
// CTA tile 64(b) x 64(s), 256 threads, 4x4 microtile, K streamed in KC chunks.
// ---------------------------------------------------------------------------
__global__ void __launch_bounds__(256) sim_kernel(const float* __restrict__ H,
                                                  const float* __restrict__ Sf) {
    __shared__ float As[Bb][KC + 1];
    __shared__ float Bs[64][KC + 1];
    const int s0 = blockIdx.x * 64;
    const int tid = threadIdx.x;
    const int tx = tid & 15, ty = tid >> 4;
    const int lb = tid >> 3;        // 0..31
    const int lk = (tid & 7) << 2;  // 0,4,...,28
    float acc[4][4] = {};

    for (int k0 = 0; k0 < Ff; k0 += KC) {
        float4 va0 = *reinterpret_cast<const float4*>(H + (size_t)lb * Ff + k0 + lk);
        float4 va1 = *reinterpret_cast<const float4*>(H + (size_t)(lb + 32) * Ff + k0 + lk);
        float4 vb0 = *reinterpret_cast<const float4*>(Sf + (size_t)(s0 + lb) * Ff + k0 + lk);
        float4 vb1 = *reinterpret_cast<const float4*>(Sf + (size_t)(s0 + lb + 32) * Ff + k0 + lk);
        __syncthreads();
        As[lb][lk] = va0.x; As[lb][lk + 1] = va0.y; As[lb][lk + 2] = va0.z; As[lb][lk + 3] = va0.w;
        As[lb + 32][lk] = va1.x; As[lb + 32][lk + 1] = va1.y; As[lb + 32][lk + 2] = va1.z; As[lb + 32][lk + 3] = va1.w;
        Bs[lb][lk] = vb0.x; Bs[lb][lk + 1] = vb0.y; Bs[lb][lk + 2] = vb0.z; Bs[lb][lk + 3] = vb0.w;
        Bs[lb + 32][lk] = vb1.x; Bs[lb + 32][lk + 1] = vb1.y; Bs[lb + 32][lk + 2] = vb1.z; Bs[lb + 32][lk + 3] = vb1.w;
        __syncthreads();
#pragma unroll
        for (int k = 0; k < KC; k++) {
            float a[4], bv[4];
#pragma unroll
            for (int i = 0; i < 4; i++) a[i] = As[ty * 4 + i][k];
#pragma unroll
            for (int j = 0; j < 4; j++) bv[j] = Bs[tx * 4 + j][k];
#pragma unroll
            for (int i = 0; i < 4; i++)
#pragma unroll
                for (int j = 0; j < 4; j++) acc[i][j] += a[i] * bv[j];
        }
    }

#pragma unroll
    for (int i = 0; i < 4; i++) {
        const int b = ty * 4 + i;
        const float hi = g_hinv[b];
#pragma unroll
        for (int j = 0; j < 4; j++) {
            const int s = s0 + tx * 4 + j;
            g_sim[(size_t)b * Ss + s] = fmaf(acc[i][j] * hi, g_sinv[s], 1.0f) * 0.5f;
        }
    }
}

// ---------------------------------------------------------------------------
// GEMM2 (split-K): part[sp][b,d] = sum_{k in slice sp} sim[b,k] * W[d,k]
// grid = 16 d-tiles x NSPLIT k-slices = 128 CTAs. Deterministic (no atomics).
// ---------------------------------------------------------------------------
__global__ void __launch_bounds__(256) agg_kernel() {
    __shared__ float As[Bb][KC + 1];
    __shared__ float Bs[64][KC + 1];
    const int nt = blockIdx.x & 15;
    const int sp = blockIdx.x >> 4;
    const int d0 = nt * 64;
    const int kb = sp * (Ss / NSPLIT);
    const int tid = threadIdx.x;
    const int tx = tid & 15, ty = tid >> 4;
    const int lb = tid >> 3;
    const int lk = (tid & 7) << 2;
    float acc[4][4] = {};

    for (int k0 = 0; k0 < Ss / NSPLIT; k0 += KC) {
        float4 va0 = *reinterpret_cast<const float4*>(g_sim + (size_t)lb * Ss + kb + k0 + lk);
        float4 va1 = *reinterpret_cast<const float4*>(g_sim + (size_t)(lb + 32) * Ss + kb + k0 + lk);
        float4 vb0 = *reinterpret_cast<const float4*>(g_W + (size_t)(d0 + lb) * Ss + kb + k0 + lk);
        float4 vb1 = *reinterpret_cast<const float4*>(g_W + (size_t)(d0 + lb + 32) * Ss + kb + k0 + lk);
        __syncthreads();
        As[lb][lk] = va0.x; As[lb][lk + 1] = va0.y; As[lb][lk + 2] = va0.z; As[lb][lk + 3] = va0.w;
        As[lb + 32][lk] = va1.x; As[lb + 32][lk + 1] = va1.y; As[lb + 32][lk + 2] = va1.z; As[lb + 32][lk + 3] = va1.w;
        Bs[lb][lk] = vb0.x; Bs[lb][lk + 1] = vb0.y; Bs[lb][lk + 2] = vb0.z; Bs[lb][lk + 3] = vb0.w;
        Bs[lb + 32][lk] = vb1.x; Bs[lb + 32][lk + 1] = vb1.y; Bs[lb + 32][lk + 2] = vb1.z; Bs[lb + 32][lk + 3] = vb1.w;
        __syncthreads();
#pragma unroll
        for (int k = 0; k < KC; k++) {
            float a[4], bv[4];
#pragma unroll
            for (int i = 0; i < 4; i++) a[i] = As[ty * 4 + i][k];
#pragma unroll
            for (int j = 0; j < 4; j++) bv[j] = Bs[tx * 4 + j][k];
#pragma unroll
            for (int i = 0; i < 4; i++)
#pragma unroll
                for (int j = 0; j < 4; j++) acc[i][j] += a[i] * bv[j];
        }
    }

#pragma unroll
    for (int i = 0; i < 4; i++)
#pragma unroll
        for (int j = 0; j < 4; j++)
            g_part[((size_t)sp * Bb + ty * 4 + i) * Dd + d0 + tx * 4 + j] = acc[i][j];
}

// ---------------------------------------------------------------------------
// Final: out[b,d] = ETA * ||grad_b|| * sum_sp part[sp][b,d]
// ---------------------------------------------------------------------------
__global__ void final_kernel(float* __restrict__ out) {
    const int idx = blockIdx.x * blockDim.x + threadIdx.x;
    if (idx >= Bb * Dd) return;
    const int b = idx >> 10;  // Dd == 1024
    float s = 0.f;
#pragma unroll
    for (int p = 0; p < NSPLIT; p++) s += g_part[(size_t)p * Bb * Dd + idx];
    out[idx] = g_gs[b] * s;
}

// ---------------------------------------------------------------------------
extern "C" void kernel_launch(void* const* d_in, const int* in_sizes, int n_in,
                              void* d_out, int out_size) {
    const float* heat = (const float*)d_in[0];  // [64,512]
    const float* grad = (const float*)d_in[1];  // [64,512]
    const float* sign = (const float*)d_in[2];  // [8192,512]
    const float* ew   = (const float*)d_in[3];  // [E]
    const int*   ed   = (const int*)d_in[4];    // [E]
    const int*   es   = (const int*)d_in[5];    // [E]
    float* out = (float*)d_out;                 // [64,1024]
    const int E = in_sizes[3];

    zero_w_kernel<<<2048, 256>>>();
    norms_kernel<<<(Ss + 2 * Bb) / 8, 256>>>(sign, heat, grad);
    scatter_kernel<<<512, 256>>>(ew, ed, es, E);
    sim_kernel<<<Ss / 64, 256>>>(heat, sign);
    agg_kernel<<<16 * NSPLIT, 256>>>();
    final_kernel<<<(Bb * Dd + 255) / 256, 256>>>(out);
}